// round 5
// baseline (speedup 1.0000x reference)
#include <cuda_runtime.h>
#include <cuda_bf16.h>
#include <mma.h>

using namespace nvcuda;

// Problem dims
#define BATCH 512
#define TSEQ  256
#define CEMB  384
#define HS    64
#define MTOT  (BATCH * TSEQ)   // 131072

// ---------------- scratch (device globals: allocation-guard safe) -------------
__device__ float g_q[MTOT * HS];   // pre-scaled by 1/sqrt(384)
__device__ float g_k[MTOT * HS];
__device__ float g_v[MTOT * HS];

__device__ __forceinline__ float to_tf32(float x) {
    return wmma::__float_to_tf32(x);
}

// =============================================================================
// Kernel 1: QKV projection  qkv = x @ w   (M=131072, N=192, K=384)
// 512 threads, CTA tile 128x192 (all of q/k/v for 128 rows), BK=32.
// 16 warps as 4x4, warp tile 32x48 (2x3 fragments). Double-buffered smem,
// register-staged prefetch, ONE sync per K-chunk. tf32 RN rounding at STS.
// q scaled by 1/sqrt(384) in epilogue.
// =============================================================================
#define PBM 128
#define PBN 192
#define PBK 32
#define A_LD 36
#define B_LD 196
#define KTILES (CEMB / PBK)   // 12
#define PROJ_SMEM_BYTES ((2 * PBM * A_LD + 2 * PBK * B_LD) * 4)  // 87040

__global__ __launch_bounds__(512, 1)
void qkv_proj_kernel(const float* __restrict__ x, const float* __restrict__ w)
{
    extern __shared__ float psm[];
    float* As0 = psm;
    float* As1 = psm + PBM * A_LD;
    float* Bs0 = psm + 2 * PBM * A_LD;
    float* Bs1 = Bs0 + PBK * B_LD;

    const int tid    = threadIdx.x;
    const int wid    = tid >> 5;
    const int m_base = blockIdx.x * PBM;

    const int wm = (wid & 3) * 32;       // 4 warp-rows x 32 = 128
    const int wn = (wid >> 2) * 48;      // 4 warp-cols x 48 = 192

    // A staging: 128x32 = 1024 float4, 2 per thread
    // B staging: 32x192 = 1536 float4, 3 per thread
    float4 a_reg[2];
    float4 b_reg[3];

    // prologue: tile 0
    #pragma unroll
    for (int j = 0; j < 2; j++) {
        const int fidx = tid + j * 512;
        a_reg[j] = *(const float4*)(x + (size_t)(m_base + (fidx >> 3)) * CEMB + (fidx & 7) * 4);
    }
    #pragma unroll
    for (int j = 0; j < 3; j++) {
        const int fidx = tid + j * 512;
        b_reg[j] = *(const float4*)(w + (size_t)(fidx / 48) * PBN + (fidx % 48) * 4);
    }
    #pragma unroll
    for (int j = 0; j < 2; j++) {
        const int fidx = tid + j * 512;
        float4 v = a_reg[j];
        v.x = to_tf32(v.x); v.y = to_tf32(v.y); v.z = to_tf32(v.z); v.w = to_tf32(v.w);
        *(float4*)(As0 + (fidx >> 3) * A_LD + (fidx & 7) * 4) = v;
    }
    #pragma unroll
    for (int j = 0; j < 3; j++) {
        const int fidx = tid + j * 512;
        float4 v = b_reg[j];
        v.x = to_tf32(v.x); v.y = to_tf32(v.y); v.z = to_tf32(v.z); v.w = to_tf32(v.w);
        *(float4*)(Bs0 + (fidx / 48) * B_LD + (fidx % 48) * 4) = v;
    }
    __syncthreads();

    wmma::fragment<wmma::accumulator, 16, 16, 8, float> acc[2][3];
    #pragma unroll
    for (int i = 0; i < 2; i++)
        #pragma unroll
        for (int j = 0; j < 3; j++)
            wmma::fill_fragment(acc[i][j], 0.0f);

    for (int t = 0; t < KTILES; t++) {
        if (t + 1 < KTILES) {
            const int k0 = (t + 1) * PBK;
            #pragma unroll
            for (int j = 0; j < 2; j++) {
                const int fidx = tid + j * 512;
                a_reg[j] = *(const float4*)(x + (size_t)(m_base + (fidx >> 3)) * CEMB + k0 + (fidx & 7) * 4);
            }
            #pragma unroll
            for (int j = 0; j < 3; j++) {
                const int fidx = tid + j * 512;
                b_reg[j] = *(const float4*)(w + (size_t)(k0 + fidx / 48) * PBN + (fidx % 48) * 4);
            }
        }

        const float* Ac = (t & 1) ? As1 : As0;
        const float* Bc = (t & 1) ? Bs1 : Bs0;
        #pragma unroll
        for (int kk = 0; kk < PBK; kk += 8) {
            wmma::fragment<wmma::matrix_a, 16, 16, 8, wmma::precision::tf32, wmma::row_major> a[2];
            wmma::fragment<wmma::matrix_b, 16, 16, 8, wmma::precision::tf32, wmma::row_major> b[3];
            #pragma unroll
            for (int i = 0; i < 2; i++)
                wmma::load_matrix_sync(a[i], Ac + (wm + i * 16) * A_LD + kk, A_LD);
            #pragma unroll
            for (int j = 0; j < 3; j++)
                wmma::load_matrix_sync(b[j], Bc + kk * B_LD + wn + j * 16, B_LD);
            #pragma unroll
            for (int i = 0; i < 2; i++)
                #pragma unroll
                for (int j = 0; j < 3; j++)
                    wmma::mma_sync(acc[i][j], a[i], b[j], acc[i][j]);
        }

        if (t + 1 < KTILES) {
            float* An = (t & 1) ? As0 : As1;
            float* Bn = (t & 1) ? Bs0 : Bs1;
            // safe to overwrite: buffer nb last read before previous barrier
            #pragma unroll
            for (int j = 0; j < 2; j++) {
                const int fidx = tid + j * 512;
                float4 v = a_reg[j];
                v.x = to_tf32(v.x); v.y = to_tf32(v.y); v.z = to_tf32(v.z); v.w = to_tf32(v.w);
                *(float4*)(An + (fidx >> 3) * A_LD + (fidx & 7) * 4) = v;
            }
            #pragma unroll
            for (int j = 0; j < 3; j++) {
                const int fidx = tid + j * 512;
                float4 v = b_reg[j];
                v.x = to_tf32(v.x); v.y = to_tf32(v.y); v.z = to_tf32(v.z); v.w = to_tf32(v.w);
                *(float4*)(Bn + (fidx / 48) * B_LD + (fidx % 48) * 4) = v;
            }
            __syncthreads();
        }
    }

    // epilogue: q slice scaled by 1/sqrt(384)
    const float scale = rsqrtf((float)CEMB);
    #pragma unroll
    for (int i = 0; i < 2; i++) {
        #pragma unroll
        for (int j = 0; j < 3; j++) {
            const int col   = wn + j * 16;
            const int slice = col >> 6;          // 0,1,2 -> q,k,v
            const int lcol  = col & 63;
            float* dst = (slice == 0) ? g_q : ((slice == 1) ? g_k : g_v);
            if (slice == 0) {
                #pragma unroll
                for (int e = 0; e < acc[i][j].num_elements; e++)
                    acc[i][j].x[e] *= scale;
            }
            wmma::store_matrix_sync(dst + (size_t)(m_base + wm + i * 16) * HS + lcol,
                                    acc[i][j], HS, wmma::mem_row_major);
        }
    }
}

// =============================================================================
// Kernel 2: fused causal attention. One CTA per (batch, 64-row query tile).
// grid = (4, 512), 256 threads. K/V streamed in 64x64 tiles with register
// prefetch. Softmax: ONE pass (mask + exp + row sum -> sInv); P left
// unnormalized (raw fp32, HW tf32-truncated at PV MMA); normalization applied
// in the epilogue via sInv while staging O through smem.
// =============================================================================
#define KV_LD 72
#define S_LD  264

#define SZ_Q  (64 * KV_LD)    // 4608
#define SZ_S  (64 * S_LD)     // 16896
#define SZ_KV (64 * KV_LD)    // 4608
#define ATT_SMEM_BYTES ((SZ_Q + SZ_S + SZ_KV + 64) * 4)   // 104704

__global__ __launch_bounds__(256, 2)
void attn_kernel(float* __restrict__ out)
{
    extern __shared__ float sm[];
    float* Qs   = sm;
    float* Ss   = Qs + SZ_Q;
    float* KVs  = Ss + SZ_S;
    float* sInv = KVs + SZ_KV;

    const int tid  = threadIdx.x;
    const int wid  = tid >> 5;
    const int lane = tid & 31;
    const int qt   = blockIdx.x;
    const int b    = blockIdx.y;
    const int nk   = (qt + 1) * 64;

    const float* Qg = g_q + (size_t)b * TSEQ * HS + (size_t)qt * 64 * HS;
    const float* Kg = g_k + (size_t)b * TSEQ * HS;
    const float* Vg = g_v + (size_t)b * TSEQ * HS;
    float*       Og = out + (size_t)b * TSEQ * HS + (size_t)qt * 64 * HS;

    const int wm = wid & 3;
    const int wn = wid >> 2;

    const int t_row = tid >> 2;
    const int t_c0  = (tid & 3) * 16;

    float4 kv_reg[4];

    // ---- prologue: load Q (pre-scaled upstream) + K tile 0 ----
    {
        float4 q_reg[4];
        #pragma unroll
        for (int i = 0; i < 4; i++)
            q_reg[i] = *(const float4*)(Qg + t_row * HS + t_c0 + i * 4);
        #pragma unroll
        for (int i = 0; i < 4; i++)
            kv_reg[i] = *(const float4*)(Kg + t_row * HS + t_c0 + i * 4);
        #pragma unroll
        for (int i = 0; i < 4; i++) {
            float4 v = q_reg[i];
            v.x = to_tf32(v.x); v.y = to_tf32(v.y); v.z = to_tf32(v.z); v.w = to_tf32(v.w);
            *(float4*)(Qs + t_row * KV_LD + t_c0 + i * 4) = v;
        }
        #pragma unroll
        for (int i = 0; i < 4; i++) {
            float4 v = kv_reg[i];
            v.x = to_tf32(v.x); v.y = to_tf32(v.y); v.z = to_tf32(v.z); v.w = to_tf32(v.w);
            *(float4*)(KVs + t_row * KV_LD + t_c0 + i * 4) = v;
        }
    }
    __syncthreads();

    // ---- S = Q K^T, streaming K tiles with register prefetch ----
    for (int kt = 0; kt <= qt; kt++) {
        if (kt < qt) {
            #pragma unroll
            for (int i = 0; i < 4; i++)
                kv_reg[i] = *(const float4*)(Kg + ((kt + 1) * 64 + t_row) * HS + t_c0 + i * 4);
        }

        wmma::fragment<wmma::accumulator, 16, 16, 8, float> sacc[2];
        wmma::fill_fragment(sacc[0], 0.0f);
        wmma::fill_fragment(sacc[1], 0.0f);
        #pragma unroll
        for (int kk = 0; kk < HS; kk += 8) {
            wmma::fragment<wmma::matrix_a, 16, 16, 8, wmma::precision::tf32, wmma::row_major> a;
            wmma::fragment<wmma::matrix_b, 16, 16, 8, wmma::precision::tf32, wmma::col_major> kb[2];
            wmma::load_matrix_sync(a, Qs + wm * 16 * KV_LD + kk, KV_LD);
            wmma::load_matrix_sync(kb[0], KVs + wn * 16 * KV_LD + kk, KV_LD);
            wmma::load_matrix_sync(kb[1], KVs + (wn + 2) * 16 * KV_LD + kk, KV_LD);
            wmma::mma_sync(sacc[0], a, kb[0], sacc[0]);
            wmma::mma_sync(sacc[1], a, kb[1], sacc[1]);
        }
        wmma::store_matrix_sync(Ss + wm * 16 * S_LD + kt * 64 + wn * 16,
                                sacc[0], S_LD, wmma::mem_row_major);
        wmma::store_matrix_sync(Ss + wm * 16 * S_LD + kt * 64 + (wn + 2) * 16,
                                sacc[1], S_LD, wmma::mem_row_major);
        __syncthreads();

        if (kt < qt) {
            #pragma unroll
            for (int i = 0; i < 4; i++) {
                float4 v = kv_reg[i];
                v.x = to_tf32(v.x); v.y = to_tf32(v.y); v.z = to_tf32(v.z); v.w = to_tf32(v.w);
                *(float4*)(KVs + t_row * KV_LD + t_c0 + i * 4) = v;
            }
            __syncthreads();
        }
    }

    // prefetch V tile 0 under softmax
    #pragma unroll
    for (int i = 0; i < 4; i++)
        kv_reg[i] = *(const float4*)(Vg + t_row * HS + t_c0 + i * 4);

    // ---- softmax: single pass (mask + exp + row sum); P left unnormalized ----
    for (int row = wid; row < 64; row += 8) {
        const int nv = qt * 64 + row + 1;          // causal valid length
        float* Sr = Ss + row * S_LD;

        float sum = 0.0f;
        for (int c = lane * 4; c < nk; c += 128) {
            float4 v = *(float4*)(Sr + c);
            float e0 = (c + 0 < nv) ? __expf(v.x) : 0.0f;
            float e1 = (c + 1 < nv) ? __expf(v.y) : 0.0f;
            float e2 = (c + 2 < nv) ? __expf(v.z) : 0.0f;
            float e3 = (c + 3 < nv) ? __expf(v.w) : 0.0f;
            sum += (e0 + e1) + (e2 + e3);
            v.x = e0; v.y = e1; v.z = e2; v.w = e3;
            *(float4*)(Sr + c) = v;
        }
        #pragma unroll
        for (int off = 16; off; off >>= 1) sum += __shfl_xor_sync(0xffffffffu, sum, off);
        if (lane == 0) sInv[row] = 1.0f / sum;
    }
    __syncthreads();

    // store prefetched V tile 0
    #pragma unroll
    for (int i = 0; i < 4; i++) {
        float4 v = kv_reg[i];
        v.x = to_tf32(v.x); v.y = to_tf32(v.y); v.z = to_tf32(v.z); v.w = to_tf32(v.w);
        *(float4*)(KVs + t_row * KV_LD + t_c0 + i * 4) = v;
    }
    __syncthreads();

    // ---- O = P V, streaming V tiles; accumulators persist in registers ----
    wmma::fragment<wmma::accumulator, 16, 16, 8, float> oacc[2];
    wmma::fill_fragment(oacc[0], 0.0f);
    wmma::fill_fragment(oacc[1], 0.0f);

    for (int kt = 0; kt <= qt; kt++) {
        if (kt < qt) {
            #pragma unroll
            for (int i = 0; i < 4; i++)
                kv_reg[i] = *(const float4*)(Vg + ((kt + 1) * 64 + t_row) * HS + t_c0 + i * 4);
        }

        #pragma unroll
        for (int kk = 0; kk < 64; kk += 8) {
            wmma::fragment<wmma::matrix_a, 16, 16, 8, wmma::precision::tf32, wmma::row_major> p;
            wmma::fragment<wmma::matrix_b, 16, 16, 8, wmma::precision::tf32, wmma::row_major> vb[2];
            wmma::load_matrix_sync(p, Ss + wm * 16 * S_LD + kt * 64 + kk, S_LD);
            wmma::load_matrix_sync(vb[0], KVs + kk * KV_LD + wn * 16, KV_LD);
            wmma::load_matrix_sync(vb[1], KVs + kk * KV_LD + (wn + 2) * 16, KV_LD);
            wmma::mma_sync(oacc[0], p, vb[0], oacc[0]);
            wmma::mma_sync(oacc[1], p, vb[1], oacc[1]);
        }
        __syncthreads();

        if (kt < qt) {
            #pragma unroll
            for (int i = 0; i < 4; i++) {
                float4 v = kv_reg[i];
                v.x = to_tf32(v.x); v.y = to_tf32(v.y); v.z = to_tf32(v.z); v.w = to_tf32(v.w);
                *(float4*)(KVs + t_row * KV_LD + t_c0 + i * 4) = v;
            }
            __syncthreads();
        }
    }

    // ---- epilogue: stage O in smem (S region is dead), normalize, write ----
    wmma::store_matrix_sync(Ss + (wm * 16) * S_LD + wn * 16, oacc[0], S_LD,
                            wmma::mem_row_major);
    wmma::store_matrix_sync(Ss + (wm * 16) * S_LD + (wn + 2) * 16, oacc[1], S_LD,
                            wmma::mem_row_major);
    __syncthreads();

    #pragma unroll
    for (int j = 0; j < 4; j++) {
        const int fidx = tid + j * 256;        // 0..1023 = 64 rows x 16 float4
        const int row  = fidx >> 4;
        const int c    = (fidx & 15) * 4;
        const float inv = sInv[row];
        float4 v = *(float4*)(Ss + row * S_LD + c);
        v.x *= inv; v.y *= inv; v.z *= inv; v.w *= inv;
        *(float4*)(Og + row * HS + c) = v;
    }
}

// =============================================================================
extern "C" void kernel_launch(void* const* d_in, const int* in_sizes, int n_in,
                              void* d_out, int out_size)
{
    const float* x = (const float*)d_in[0];     // [512,256,384]
    const float* w = (const float*)d_in[1];     // [384,192]
    float* out = (float*)d_out;                 // [512,256,64]

    (void)in_sizes; (void)n_in; (void)out_size;

    static bool attr_set = false;
    if (!attr_set) {
        cudaFuncSetAttribute(qkv_proj_kernel, cudaFuncAttributeMaxDynamicSharedMemorySize,
                             PROJ_SMEM_BYTES);
        cudaFuncSetAttribute(attn_kernel, cudaFuncAttributeMaxDynamicSharedMemorySize,
                             ATT_SMEM_BYTES);
        attr_set = true;
    }

    qkv_proj_kernel<<<MTOT / PBM, 512, PROJ_SMEM_BYTES>>>(x, w);
    attn_kernel<<<dim3(4, BATCH), 256, ATT_SMEM_BYTES>>>(out);
}

// round 6
// speedup vs baseline: 3.1269x; 3.1269x over previous
#include <cuda_runtime.h>
#include <cuda_fp16.h>
#include <mma.h>

using namespace nvcuda;

// Problem dims
#define BATCH 512
#define TSEQ  256
#define CEMB  384
#define HS    64
#define MTOT  (BATCH * TSEQ)   // 131072

// ---------------- scratch (device globals: allocation-guard safe) -------------
__device__ float g_q[MTOT * HS];
__device__ float g_k[MTOT * HS];
__device__ float g_v[MTOT * HS];

struct alignas(16) H8 { __half2 h[4]; };

__device__ __forceinline__ H8 pack8(float4 a, float4 b) {
    H8 r;
    r.h[0] = __floats2half2_rn(a.x, a.y);
    r.h[1] = __floats2half2_rn(a.z, a.w);
    r.h[2] = __floats2half2_rn(b.x, b.y);
    r.h[3] = __floats2half2_rn(b.z, b.w);
    return r;
}

// =============================================================================
// Kernel 1: QKV projection  qkv = x @ w   (M=131072, N=192, K=384), fp16 MMA.
// 256 threads, CTA tile 64x192, BK=32. 8 warps (2x4), warp tile 32x48.
// Double-buffered half smem + register prefetch; fp16 rounding at STS;
// fp32 accumulate; fp32 outputs.
// =============================================================================
#define PBM 64
#define PBN 192
#define PBK 32
#define A_LDH 40     // halves (80B stride: conflict-free 8-row phases)
#define B_LDH 200    // halves (400B stride)
#define KTILES (CEMB / PBK)   // 12

__global__ __launch_bounds__(256, 2)
void qkv_proj_kernel(const float* __restrict__ x, const float* __restrict__ w)
{
    __shared__ __half As[2][PBM * A_LDH];   // 2 x 5120B
    __shared__ __half Bs[2][PBK * B_LDH];   // 2 x 12800B

    const int tid    = threadIdx.x;
    const int wid    = tid >> 5;
    const int m_base = blockIdx.x * PBM;

    const int wm = (wid & 1) * 32;       // 2 warp-rows
    const int wn = (wid >> 1) * 48;      // 4 warp-cols

    // A staging: row = tid>>2 (0..63), c0 = (tid&3)*8, 8 floats -> 8 halves
    const int a_row = tid >> 2;
    const int a_c0  = (tid & 3) * 8;
    // B staging: row = tid>>3 (0..31), c0 = (tid&7)*24, 24 floats -> 24 halves
    const int b_row = tid >> 3;
    const int b_c0  = (tid & 7) * 24;

    const float* xA = x + (size_t)(m_base + a_row) * CEMB + a_c0;
    const float* wB = w + (size_t)b_row * PBN + b_c0;

    float4 a_reg[2];
    float4 b_reg[6];

    // prologue: tile 0
    #pragma unroll
    for (int i = 0; i < 2; i++) a_reg[i] = *(const float4*)(xA + i * 4);
    #pragma unroll
    for (int i = 0; i < 6; i++) b_reg[i] = *(const float4*)(wB + i * 4);

    *(H8*)(As[0] + a_row * A_LDH + a_c0) = pack8(a_reg[0], a_reg[1]);
    #pragma unroll
    for (int i = 0; i < 3; i++)
        *(H8*)(Bs[0] + b_row * B_LDH + b_c0 + i * 8) = pack8(b_reg[2 * i], b_reg[2 * i + 1]);
    __syncthreads();

    wmma::fragment<wmma::accumulator, 16, 16, 16, float> acc[2][3];
    #pragma unroll
    for (int i = 0; i < 2; i++)
        #pragma unroll
        for (int j = 0; j < 3; j++)
            wmma::fill_fragment(acc[i][j], 0.0f);

    for (int t = 0; t < KTILES; t++) {
        if (t + 1 < KTILES) {
            const int k0 = (t + 1) * PBK;
            #pragma unroll
            for (int i = 0; i < 2; i++) a_reg[i] = *(const float4*)(xA + k0 + i * 4);
            const float* wn2 = wB + (size_t)k0 * PBN;
            #pragma unroll
            for (int i = 0; i < 6; i++) b_reg[i] = *(const float4*)(wn2 + i * 4);
        }

        const __half* Ac = As[t & 1];
        const __half* Bc = Bs[t & 1];
        #pragma unroll
        for (int kk = 0; kk < PBK; kk += 16) {
            wmma::fragment<wmma::matrix_a, 16, 16, 16, __half, wmma::row_major> a[2];
            wmma::fragment<wmma::matrix_b, 16, 16, 16, __half, wmma::row_major> b[3];
            #pragma unroll
            for (int i = 0; i < 2; i++)
                wmma::load_matrix_sync(a[i], Ac + (wm + i * 16) * A_LDH + kk, A_LDH);
            #pragma unroll
            for (int j = 0; j < 3; j++)
                wmma::load_matrix_sync(b[j], Bc + kk * B_LDH + wn + j * 16, B_LDH);
            #pragma unroll
            for (int i = 0; i < 2; i++)
                #pragma unroll
                for (int j = 0; j < 3; j++)
                    wmma::mma_sync(acc[i][j], a[i], b[j], acc[i][j]);
        }

        if (t + 1 < KTILES) {
            __half* An = As[(t + 1) & 1];
            __half* Bn = Bs[(t + 1) & 1];
            __syncthreads();
            *(H8*)(An + a_row * A_LDH + a_c0) = pack8(a_reg[0], a_reg[1]);
            #pragma unroll
            for (int i = 0; i < 3; i++)
                *(H8*)(Bn + b_row * B_LDH + b_c0 + i * 8) = pack8(b_reg[2 * i], b_reg[2 * i + 1]);
            __syncthreads();
        }
    }

    // store: global column decides q/k/v slice (fp32 outputs)
    #pragma unroll
    for (int i = 0; i < 2; i++) {
        #pragma unroll
        for (int j = 0; j < 3; j++) {
            const int col   = wn + j * 16;
            const int slice = col >> 6;          // 0,1,2 -> q,k,v
            const int lcol  = col & 63;
            float* dst = (slice == 0) ? g_q : ((slice == 1) ? g_k : g_v);
            wmma::store_matrix_sync(dst + (size_t)(m_base + wm + i * 16) * HS + lcol,
                                    acc[i][j], HS, wmma::mem_row_major);
        }
    }
}

// =============================================================================
// Kernel 2: fused causal attention, fp16 MMA. One CTA per (batch, 64-row
// query tile), grid (4, 512), 256 threads. K/V streamed in 64x64 half tiles
// with register prefetch. S accumulated fp32 in smem; softmax in one
// register-staged pass per row, normalized half P written IN-PLACE over S.
// =============================================================================
#define KV_LDH 72     // halves (144B stride: conflict-free)
#define S_LDF  264    // floats
#define P_LDH  528    // halves (same bytes as S row)

#define QB_BYTES  (64 * KV_LDH * 2)   // 9216
#define KVB_BYTES (64 * KV_LDH * 2)   // 9216
#define SB_BYTES  (64 * S_LDF * 4)    // 67584
#define ATT_SMEM_BYTES (QB_BYTES + KVB_BYTES + SB_BYTES)   // 86016

__global__ __launch_bounds__(256, 2)
void attn_kernel(float* __restrict__ out)
{
    extern __shared__ char smraw[];
    __half* Qs  = (__half*)smraw;
    __half* KVs = (__half*)(smraw + QB_BYTES);
    float*  Ss  = (float*)(smraw + QB_BYTES + KVB_BYTES);
    __half* Ps  = (__half*)Ss;                 // alias: P overwrites dead S

    const int tid  = threadIdx.x;
    const int wid  = tid >> 5;
    const int lane = tid & 31;
    const int qt   = blockIdx.x;
    const int b    = blockIdx.y;

    const float* Qg = g_q + (size_t)b * TSEQ * HS + (size_t)qt * 64 * HS;
    const float* Kg = g_k + (size_t)b * TSEQ * HS;
    const float* Vg = g_v + (size_t)b * TSEQ * HS;
    float*       Og = out + (size_t)b * TSEQ * HS + (size_t)qt * 64 * HS;

    const float scale = rsqrtf((float)CEMB);   // 1/sqrt(384), per reference

    const int wm = wid & 3;            // warp's m tile
    const int wn = wid >> 2;           // warp's first n tile; second = wn+2

    const int t_row = tid >> 2;        // 0..63
    const int t_c0  = (tid & 3) * 16;  // 16 floats per thread

    float4 kv_reg[4];

    // ---- prologue: load Q (scale folded in) + K tile 0 ----
    {
        float4 q_reg[4];
        #pragma unroll
        for (int i = 0; i < 4; i++)
            q_reg[i] = *(const float4*)(Qg + t_row * HS + t_c0 + i * 4);
        #pragma unroll
        for (int i = 0; i < 4; i++)
            kv_reg[i] = *(const float4*)(Kg + t_row * HS + t_c0 + i * 4);
        #pragma unroll
        for (int i = 0; i < 4; i++) {
            q_reg[i].x *= scale; q_reg[i].y *= scale;
            q_reg[i].z *= scale; q_reg[i].w *= scale;
        }
        *(H8*)(Qs + t_row * KV_LDH + t_c0)     = pack8(q_reg[0], q_reg[1]);
        *(H8*)(Qs + t_row * KV_LDH + t_c0 + 8) = pack8(q_reg[2], q_reg[3]);
        *(H8*)(KVs + t_row * KV_LDH + t_c0)     = pack8(kv_reg[0], kv_reg[1]);
        *(H8*)(KVs + t_row * KV_LDH + t_c0 + 8) = pack8(kv_reg[2], kv_reg[3]);
    }
    __syncthreads();

    // ---- S = Q K^T, streaming K tiles with register prefetch ----
    for (int kt = 0; kt <= qt; kt++) {
        if (kt < qt) {
            #pragma unroll
            for (int i = 0; i < 4; i++)
                kv_reg[i] = *(const float4*)(Kg + ((kt + 1) * 64 + t_row) * HS + t_c0 + i * 4);
        }

        wmma::fragment<wmma::accumulator, 16, 16, 16, float> sacc[2];
        wmma::fill_fragment(sacc[0], 0.0f);
        wmma::fill_fragment(sacc[1], 0.0f);
        #pragma unroll
        for (int kk = 0; kk < HS; kk += 16) {
            wmma::fragment<wmma::matrix_a, 16, 16, 16, __half, wmma::row_major> a;
            wmma::fragment<wmma::matrix_b, 16, 16, 16, __half, wmma::col_major> kb[2];
            wmma::load_matrix_sync(a, Qs + wm * 16 * KV_LDH + kk, KV_LDH);
            wmma::load_matrix_sync(kb[0], KVs + wn * 16 * KV_LDH + kk, KV_LDH);
            wmma::load_matrix_sync(kb[1], KVs + (wn + 2) * 16 * KV_LDH + kk, KV_LDH);
            wmma::mma_sync(sacc[0], a, kb[0], sacc[0]);
            wmma::mma_sync(sacc[1], a, kb[1], sacc[1]);
        }
        wmma::store_matrix_sync(Ss + wm * 16 * S_LDF + kt * 64 + wn * 16,
                                sacc[0], S_LDF, wmma::mem_row_major);
        wmma::store_matrix_sync(Ss + wm * 16 * S_LDF + kt * 64 + (wn + 2) * 16,
                                sacc[1], S_LDF, wmma::mem_row_major);
        __syncthreads();

        if (kt < qt) {
            *(H8*)(KVs + t_row * KV_LDH + t_c0)     = pack8(kv_reg[0], kv_reg[1]);
            *(H8*)(KVs + t_row * KV_LDH + t_c0 + 8) = pack8(kv_reg[2], kv_reg[3]);
            __syncthreads();
        }
    }

    // prefetch V tile 0 under softmax
    #pragma unroll
    for (int i = 0; i < 4; i++)
        kv_reg[i] = *(const float4*)(Vg + t_row * HS + t_c0 + i * 4);

    // ---- softmax: one register-staged pass per row; half P in-place ----
    for (int row = wid; row < 64; row += 8) {
        const int nv = qt * 64 + row + 1;          // causal valid length
        float*  Sr = Ss + row * S_LDF;
        __half* Pr = Ps + row * P_LDH;

        float ex[8];
        float sum = 0.0f;
        #pragma unroll
        for (int j = 0; j < 4; j++) {
            if (j <= qt) {
                const int c = lane * 2 + j * 64;
                float2 v = *(float2*)(Sr + c);
                float e0 = (c     < nv) ? __expf(v.x) : 0.0f;
                float e1 = (c + 1 < nv) ? __expf(v.y) : 0.0f;
                ex[2 * j] = e0; ex[2 * j + 1] = e1;
                sum += e0 + e1;
            }
        }
        #pragma unroll
        for (int off = 16; off; off >>= 1) sum += __shfl_xor_sync(0xffffffffu, sum, off);
        const float inv = 1.0f / sum;

        __syncwarp();   // all S reads for this row complete before P overwrites
        #pragma unroll
        for (int j = 0; j < 4; j++) {
            if (j <= qt) {
                const int c = lane * 2 + j * 64;
                *(__half2*)(Pr + c) = __floats2half2_rn(ex[2 * j] * inv, ex[2 * j + 1] * inv);
            }
        }
    }
    __syncthreads();

    // store prefetched V tile 0
    *(H8*)(KVs + t_row * KV_LDH + t_c0)     = pack8(kv_reg[0], kv_reg[1]);
    *(H8*)(KVs + t_row * KV_LDH + t_c0 + 8) = pack8(kv_reg[2], kv_reg[3]);
    __syncthreads();

    // ---- O = P V, streaming V tiles; accumulators persist in registers ----
    wmma::fragment<wmma::accumulator, 16, 16, 16, float> oacc[2];
    wmma::fill_fragment(oacc[0], 0.0f);
    wmma::fill_fragment(oacc[1], 0.0f);

    for (int kt = 0; kt <= qt; kt++) {
        if (kt < qt) {
            #pragma unroll
            for (int i = 0; i < 4; i++)
                kv_reg[i] = *(const float4*)(Vg + ((kt + 1) * 64 + t_row) * HS + t_c0 + i * 4);
        }

        #pragma unroll
        for (int kk = 0; kk < 64; kk += 16) {
            wmma::fragment<wmma::matrix_a, 16, 16, 16, __half, wmma::row_major> p;
            wmma::fragment<wmma::matrix_b, 16, 16, 16, __half, wmma::row_major> vb[2];
            wmma::load_matrix_sync(p, Ps + wm * 16 * P_LDH + kt * 64 + kk, P_LDH);
            wmma::load_matrix_sync(vb[0], KVs + kk * KV_LDH + wn * 16, KV_LDH);
            wmma::load_matrix_sync(vb[1], KVs + kk * KV_LDH + (wn + 2) * 16, KV_LDH);
            wmma::mma_sync(oacc[0], p, vb[0], oacc[0]);
            wmma::mma_sync(oacc[1], p, vb[1], oacc[1]);
        }
        __syncthreads();

        if (kt < qt) {
            *(H8*)(KVs + t_row * KV_LDH + t_c0)     = pack8(kv_reg[0], kv_reg[1]);
            *(H8*)(KVs + t_row * KV_LDH + t_c0 + 8) = pack8(kv_reg[2], kv_reg[3]);
            __syncthreads();
        }
    }

    wmma::store_matrix_sync(Og + (wm * 16) * HS + wn * 16, oacc[0], HS,
                            wmma::mem_row_major);
    wmma::store_matrix_sync(Og + (wm * 16) * HS + (wn + 2) * 16, oacc[1], HS,
                            wmma::mem_row_major);
}

// =============================================================================
extern "C" void kernel_launch(void* const* d_in, const int* in_sizes, int n_in,
                              void* d_out, int out_size)
{
    const float* x = (const float*)d_in[0];     // [512,256,384]
    const float* w = (const float*)d_in[1];     // [384,192]
    float* out = (float*)d_out;                 // [512,256,64]

    (void)in_sizes; (void)n_in; (void)out_size;

    static bool attr_set = false;
    if (!attr_set) {
        cudaFuncSetAttribute(attn_kernel, cudaFuncAttributeMaxDynamicSharedMemorySize,
                             ATT_SMEM_BYTES);
        attr_set = true;
    }

    qkv_proj_kernel<<<MTOT / PBM, 256>>>(x, w);
    attn_kernel<<<dim3(4, BATCH), 256, ATT_SMEM_BYTES>>>(out);
}